// round 3
// baseline (speedup 1.0000x reference)
#include <cuda_runtime.h>
#include <cstdint>
#include <cstddef>

// Problem sizes (fixed by the reference)
#define HH     256
#define G4     1024
#define BB     256
#define TT     512
#define DD     64
#define NCLASS 10

// Recurrent kernel config
#define CS   8     // CTAs per cluster
#define NC   16    // clusters  -> 128 CTAs total, 1 per SM
#define BC   16    // batch rows per cluster
#define GJ   32    // hidden (j) columns per CTA
#define RTH  512   // threads per CTA (16 warps -> 4 per SMSP)
#define HPAD 264   // padded row stride for H-wide smem rows (floats)
#define DPAD 72    // padded row stride for D-wide smem rows (floats)

// Shared layout (floats)
#define WS_OFF   0                         // W_hh slice: [4*GJ][HPAD]
#define WIS_OFF  (4 * GJ * HPAD)           // W_ih slice: [4*GJ][DPAD]
#define HS_OFF   (WIS_OFF + 4 * GJ * DPAD) // h tile:     [BC][HPAD]
#define XS_OFF   (HS_OFF + BC * HPAD)      // x tile:     [BC][DPAD]
#define REC_SMEM ((XS_OFF + BC * DPAD) * 4)

// Global state: double-buffered hidden state (c stays in registers)
__device__ float g_h[2][BB * HH];

__device__ __forceinline__ float sigm(float x) {
    return 1.0f / (1.0f + __expf(-x));
}
__device__ __forceinline__ float tanh_fast(float x) {
    return 1.0f - 2.0f / (__expf(2.0f * x) + 1.0f);
}

// Packed dual-fp32 FMA (SASS FFMA2): acc.lo += a.lo*b.lo; acc.hi += a.hi*b.hi
#define PFMA(acc, A, B) \
    asm("fma.rn.f32x2 %0, %1, %2, %0;" : "+l"(acc) : "l"(A), "l"(B))
#define ACCP(g, i, W, V)                 \
    do {                                 \
        PFMA(acc2[g][i], (W).x, (V).x);  \
        PFMA(acc2[g][i], (W).y, (V).y);  \
    } while (0)

// dummy kernel to steer ncu's skip-count onto lstm_kernel
__global__ void sep_kernel() {}

// ---------------------------------------------------------------------------
// Persistent recurrent kernel.
// Cluster q owns batch rows [q*BC,(q+1)*BC). CTA rank r owns hidden cols
// [r*GJ,(r+1)*GJ), i.e. gate rows {g*256 + r*32 + jl}.
// tid = jl*16 + bgrp*4 + kq :
//   jl in [0,32): hidden col;  bgrp in [0,4): base batch lane;
//   kq in [0,4): k-quarter (chunks of 4 floats, stride 16).
// acc2[gate][i] = packed partial sums for batch rows bl = bgrp + 4*i over this
// thread's k-quarter; shfl-xor(1), shfl-xor(2) reduce over kq. After reduction
// the thread owns batch row bl = bgrp + 4*kq (i = kq) for the pointwise update.
// ---------------------------------------------------------------------------
__global__ __launch_bounds__(RTH, 1) __cluster_dims__(CS, 1, 1)
void lstm_kernel(const float* __restrict__ x,
                 const float* __restrict__ Wih,
                 const float* __restrict__ Whh,
                 const float* __restrict__ bih,
                 const float* __restrict__ bhh) {
    extern __shared__ float sm[];
    float* Ws  = sm + WS_OFF;
    float* Wis = sm + WIS_OFF;
    float* hs  = sm + HS_OFF;
    float* xs  = sm + XS_OFF;

    const int cta  = blockIdx.x;
    const int q    = cta / CS;
    const int r    = cta % CS;
    const int tid  = threadIdx.x;
    const int jl   = tid >> 4;         // [0,32)
    const int bgrp = (tid >> 2) & 3;   // [0,4)
    const int kq   = tid & 3;          // [0,4)
    const int jg   = r * GJ + jl;

    // ---- zero this CTA's slice of h[0] (cluster-visible after the arrive) ----
    for (int f = tid; f < BC * GJ; f += RTH) {
        int bl = f >> 5, c = f & 31;
        g_h[0][(q * BC + bl) * HH + r * GJ + c] = 0.0f;
    }

    // ---- one-time weight loads ----
    for (int f = tid; f < 128 * 64; f += RTH) {
        int row = f >> 6, c4 = (f & 63) << 2;
        int g = row >> 5, j2 = row & 31;
        float4 v = *reinterpret_cast<const float4*>(
            &Whh[(size_t)(g * HH + r * GJ + j2) * HH + c4]);
        *reinterpret_cast<float4*>(&Ws[row * HPAD + c4]) = v;
    }
    for (int f = tid; f < 128 * 16; f += RTH) {
        int row = f >> 4, d4 = (f & 15) << 2;
        int g = row >> 5, j2 = row & 31;
        float4 v = *reinterpret_cast<const float4*>(
            &Wih[(size_t)(g * HH + r * GJ + j2) * DD + d4]);
        *reinterpret_cast<float4*>(&Wis[row * DPAD + d4]) = v;
    }

    float biasv[4];
#pragma unroll
    for (int g = 0; g < 4; g++)
        biasv[g] = bih[g * HH + jg] + bhh[g * HH + jg];

    // owned batch row after reduction (i = kq)
    const int blo = bgrp + 4 * kq;
    const int bog = q * BC + blo;

    // x prefetch for t = 0 (first 256 threads handle the 16x64 tile)
    const int xbl = (tid >> 4) & 15, xd4 = (tid & 15) << 2;
    const bool xldr = (tid < 256);
    const float* xbase = &x[(size_t)(q * BC + xbl) * TT * DD + xd4];
    float4 xreg = make_float4(0.f, 0.f, 0.f, 0.f);
    if (xldr) xreg = *reinterpret_cast<const float4*>(xbase);

    float cstate = 0.0f;
    __syncthreads();   // weights + zero slice in place (CTA-local)
    asm volatile("barrier.cluster.arrive.aligned;" ::: "memory");

    for (int t = 0; t < TT; t++) {
        // ---- publish x(t) to smem, kick off prefetch of x(t+1) ----
        if (xldr) {
            *reinterpret_cast<float4*>(&xs[xbl * DPAD + xd4]) = xreg;
            if (t + 1 < TT)
                xreg = *reinterpret_cast<const float4*>(xbase + (size_t)(t + 1) * DD);
        }
        __syncthreads();   // xs ready; also: all warps done with hs of t-1

        unsigned long long acc2[4][4];
#pragma unroll
        for (int g = 0; g < 4; g++)
#pragma unroll
            for (int i = 0; i < 4; i++) acc2[g][i] = 0ull;

        // ---- input projection (independent of h -> hides cluster.wait) ----
        {
            const float* wp = Wis + jl * DPAD + kq * 4;
            const float* xp = xs + bgrp * DPAD + kq * 4;
#pragma unroll 2
            for (int cc = 0; cc < 4; cc++) {
                int d = cc * 16;
                ulonglong2 w0 = *reinterpret_cast<const ulonglong2*>(&wp[d + 0 * GJ * DPAD]);
                ulonglong2 w1 = *reinterpret_cast<const ulonglong2*>(&wp[d + 1 * GJ * DPAD]);
                ulonglong2 w2 = *reinterpret_cast<const ulonglong2*>(&wp[d + 2 * GJ * DPAD]);
                ulonglong2 w3 = *reinterpret_cast<const ulonglong2*>(&wp[d + 3 * GJ * DPAD]);
                ulonglong2 v0 = *reinterpret_cast<const ulonglong2*>(&xp[d + 0 * DPAD]);
                ulonglong2 v1 = *reinterpret_cast<const ulonglong2*>(&xp[d + 4 * DPAD]);
                ulonglong2 v2 = *reinterpret_cast<const ulonglong2*>(&xp[d + 8 * DPAD]);
                ulonglong2 v3 = *reinterpret_cast<const ulonglong2*>(&xp[d + 12 * DPAD]);
                ACCP(0,0,w0,v0); ACCP(0,1,w0,v1); ACCP(0,2,w0,v2); ACCP(0,3,w0,v3);
                ACCP(1,0,w1,v0); ACCP(1,1,w1,v1); ACCP(1,2,w1,v2); ACCP(1,3,w1,v3);
                ACCP(2,0,w2,v0); ACCP(2,1,w2,v1); ACCP(2,2,w2,v2); ACCP(2,3,w2,v3);
                ACCP(3,0,w3,v0); ACCP(3,1,w3,v1); ACCP(3,2,w3,v2); ACCP(3,3,w3,v3);
            }
        }

        // ---- h(t-1) now published by all peer CTAs ----
        asm volatile("barrier.cluster.wait.aligned;" ::: "memory");

        const float* hsrc = g_h[t & 1];
        float* hdst = g_h[(t + 1) & 1];

#pragma unroll
        for (int ii = 0; ii < 2; ii++) {
            int f = tid + RTH * ii;            // [0,1024)
            int bl = f >> 6, c4 = (f & 63) << 2;
            float4 v = __ldcg(reinterpret_cast<const float4*>(
                &hsrc[(q * BC + bl) * HH + c4]));
            *reinterpret_cast<float4*>(&hs[bl * HPAD + c4]) = v;
        }
        __syncthreads();   // hs ready

        // ---- recurrent part: k over H=256, this thread's quarter ----
        {
            const float* wp = Ws + jl * HPAD + kq * 4;
            const float* hp = hs + bgrp * HPAD + kq * 4;
#pragma unroll 2
            for (int cc = 0; cc < 16; cc++) {
                int k = cc * 16;
                ulonglong2 w0 = *reinterpret_cast<const ulonglong2*>(&wp[k + 0 * GJ * HPAD]);
                ulonglong2 w1 = *reinterpret_cast<const ulonglong2*>(&wp[k + 1 * GJ * HPAD]);
                ulonglong2 w2 = *reinterpret_cast<const ulonglong2*>(&wp[k + 2 * GJ * HPAD]);
                ulonglong2 w3 = *reinterpret_cast<const ulonglong2*>(&wp[k + 3 * GJ * HPAD]);
                ulonglong2 v0 = *reinterpret_cast<const ulonglong2*>(&hp[k + 0 * HPAD]);
                ulonglong2 v1 = *reinterpret_cast<const ulonglong2*>(&hp[k + 4 * HPAD]);
                ulonglong2 v2 = *reinterpret_cast<const ulonglong2*>(&hp[k + 8 * HPAD]);
                ulonglong2 v3 = *reinterpret_cast<const ulonglong2*>(&hp[k + 12 * HPAD]);
                ACCP(0,0,w0,v0); ACCP(0,1,w0,v1); ACCP(0,2,w0,v2); ACCP(0,3,w0,v3);
                ACCP(1,0,w1,v0); ACCP(1,1,w1,v1); ACCP(1,2,w1,v2); ACCP(1,3,w1,v3);
                ACCP(2,0,w2,v0); ACCP(2,1,w2,v1); ACCP(2,2,w2,v2); ACCP(2,3,w2,v3);
                ACCP(3,0,w3,v0); ACCP(3,1,w3,v1); ACCP(3,2,w3,v2); ACCP(3,3,w3,v3);
            }
        }

        // ---- unpack packed partials, reduce across k-quarters (kq = tid bits 0-1) ----
        float red[4][4];
#pragma unroll
        for (int g = 0; g < 4; g++)
#pragma unroll
            for (int i = 0; i < 4; i++) {
                float lo = __uint_as_float((unsigned)acc2[g][i]);
                float hi = __uint_as_float((unsigned)(acc2[g][i] >> 32));
                float a = lo + hi;
                a += __shfl_xor_sync(0xffffffffu, a, 1);
                a += __shfl_xor_sync(0xffffffffu, a, 2);
                red[g][i] = a;
            }

        // this thread's owned batch row corresponds to i = kq (branch-free select)
        float z[4];
#pragma unroll
        for (int g = 0; g < 4; g++) {
            float a01 = (kq & 1) ? red[g][1] : red[g][0];
            float a23 = (kq & 1) ? red[g][3] : red[g][2];
            z[g] = ((kq & 2) ? a23 : a01) + biasv[g];
        }
        {
            float ig = sigm(z[0]), fg = sigm(z[1]);
            float gg = tanh_fast(z[2]), og = sigm(z[3]);
            cstate = fg * cstate + ig * gg;
            hdst[bog * HH + jg] = og * tanh_fast(cstate);
        }

        // release this step's h to the cluster
        asm volatile("barrier.cluster.arrive.aligned;" ::: "memory");
    }
    asm volatile("barrier.cluster.wait.aligned;" ::: "memory");
}

// Final projection: out[b][c] = sigmoid(h_T[b] . W_out[c] + b_out[c]);
// h_T lives in g_h[0] (TT = 512 even).
__global__ void out_kernel(const float* __restrict__ Wout,
                           const float* __restrict__ bout,
                           float* __restrict__ out) {
    int b = blockIdx.x;
    int w = threadIdx.x >> 5, lane = threadIdx.x & 31;
    if (w >= NCLASS) return;
    float s = 0.0f;
#pragma unroll
    for (int k = lane; k < HH; k += 32)
        s += g_h[0][b * HH + k] * Wout[w * HH + k];
#pragma unroll
    for (int o = 16; o; o >>= 1) s += __shfl_xor_sync(0xffffffffu, s, o);
    if (lane == 0) out[b * NCLASS + w] = sigm(s + bout[w]);
}

extern "C" void kernel_launch(void* const* d_in, const int* in_sizes, int n_in,
                              void* d_out, int out_size) {
    const float* x    = (const float*)d_in[0];
    const float* Wih  = (const float*)d_in[1];
    const float* Whh  = (const float*)d_in[2];
    const float* bih  = (const float*)d_in[3];
    const float* bhh  = (const float*)d_in[4];
    const float* Wout = (const float*)d_in[5];
    const float* bout = (const float*)d_in[6];
    float* out = (float*)d_out;

    cudaFuncSetAttribute(lstm_kernel,
                         cudaFuncAttributeMaxDynamicSharedMemorySize, REC_SMEM);

    // 4 launches/iteration: ncu's "-s 5 -c 1" (skip 5) lands on lstm_kernel.
    sep_kernel<<<1, 32>>>();
    lstm_kernel<<<NC * CS, RTH, REC_SMEM>>>(x, Wih, Whh, bih, bhh);
    out_kernel<<<BB, 32 * NCLASS>>>(Wout, bout, out);
    sep_kernel<<<1, 32>>>();
}

// round 4
// speedup vs baseline: 1.6517x; 1.6517x over previous
#include <cuda_runtime.h>
#include <cstdint>
#include <cstddef>

// Problem sizes (fixed by the reference)
#define HH     256
#define G4     1024
#define BB     256
#define TT     512
#define DD     64
#define NCLASS 10

// Recurrent kernel config
#define CS   8     // CTAs per cluster
#define NC   16    // clusters  -> 128 CTAs total, 1 per SM
#define BC   16    // batch rows per cluster
#define GJ   32    // hidden (j) columns per CTA
#define RTH  256   // threads per CTA (proven best layout)
#define HPAD 264   // padded row stride for H-wide smem rows (floats)
#define DPAD 72    // padded row stride for D-wide smem rows (floats)

// Shared layout (floats)
#define WS_OFF   0                          // W_hh slice: [4*GJ][HPAD]
#define WIS_OFF  (4 * GJ * HPAD)            // W_ih slice: [4*GJ][DPAD]
#define HS_OFF   (WIS_OFF + 4 * GJ * DPAD)  // h tile:     [BC][HPAD]
#define XS_OFF   (HS_OFF + BC * HPAD)       // x tiles:    [2][BC][DPAD]
#define REC_SMEM ((XS_OFF + 2 * BC * DPAD) * 4)

// Global state: double-buffered hidden state (c stays in registers)
__device__ float g_h[2][BB * HH];

__device__ __forceinline__ float sigm(float x) {
    return 1.0f / (1.0f + __expf(-x));
}
__device__ __forceinline__ float tanh_fast(float x) {
    return 1.0f - 2.0f / (__expf(2.0f * x) + 1.0f);
}

// Packed dual-fp32 FMA (SASS FFMA2): acc.lo += a.lo*b.lo; acc.hi += a.hi*b.hi
#define PFMA(acc, A, B) \
    asm("fma.rn.f32x2 %0, %1, %2, %0;" : "+l"(acc) : "l"(A), "l"(B))
#define ACCP(g, i, W, V)                 \
    do {                                 \
        PFMA(acc2[g][i], (W).x, (V).x);  \
        PFMA(acc2[g][i], (W).y, (V).y);  \
    } while (0)

// ---------------------------------------------------------------------------
// Single fused persistent kernel: h0-zero + 512-step recurrence + output head.
// Cluster q owns batch rows [q*BC,(q+1)*BC). CTA rank r owns hidden cols
// [r*GJ,(r+1)*GJ), i.e. gate rows {g*256 + r*32 + jl}.
// tid = jl*8 + bgrp*2 + kh :
//   jl in [0,32) hidden col; bgrp in [0,4) base batch lane; kh in {0,1} k-half.
// acc2[gate][i] holds packed partial sums for batch rows bl = bgrp + 4*i over
// this thread's k-half; partner tid^1 holds the other half (shfl-xor reduce).
// Thread then owns batch rows {bgrp+8*kh, bgrp+4+8*kh} for the pointwise update.
// Per step: ONE __syncthreads; the cluster barrier provides the other ordering.
// ---------------------------------------------------------------------------
__global__ __launch_bounds__(RTH, 1) __cluster_dims__(CS, 1, 1)
void lstm_kernel(const float* __restrict__ x,
                 const float* __restrict__ Wih,
                 const float* __restrict__ Whh,
                 const float* __restrict__ bih,
                 const float* __restrict__ bhh,
                 const float* __restrict__ Wout,
                 const float* __restrict__ bout,
                 float* __restrict__ out) {
    extern __shared__ float sm[];
    float* Ws  = sm + WS_OFF;
    float* Wis = sm + WIS_OFF;
    float* hs  = sm + HS_OFF;
    float* xs  = sm + XS_OFF;       // two slots of BC*DPAD

    const int cta  = blockIdx.x;
    const int q    = cta / CS;
    const int r    = cta % CS;
    const int tid  = threadIdx.x;
    const int jl   = tid >> 3;
    const int bgrp = (tid >> 1) & 3;
    const int kh   = tid & 1;
    const int jg   = r * GJ + jl;

    // ---- zero this CTA's slice of h[0] (published by the pre-loop arrive) ----
    for (int f = tid; f < BC * GJ; f += RTH) {
        int bl = f >> 5, c = f & 31;
        g_h[0][(q * BC + bl) * HH + r * GJ + c] = 0.0f;
    }

    // ---- one-time weight loads ----
    for (int f = tid; f < 128 * 64; f += RTH) {
        int row = f >> 6, c4 = (f & 63) << 2;
        int g = row >> 5, j2 = row & 31;
        float4 v = *reinterpret_cast<const float4*>(
            &Whh[(size_t)(g * HH + r * GJ + j2) * HH + c4]);
        *reinterpret_cast<float4*>(&Ws[row * HPAD + c4]) = v;
    }
    for (int f = tid; f < 128 * 16; f += RTH) {
        int row = f >> 4, d4 = (f & 15) << 2;
        int g = row >> 5, j2 = row & 31;
        float4 v = *reinterpret_cast<const float4*>(
            &Wih[(size_t)(g * HH + r * GJ + j2) * DD + d4]);
        *reinterpret_cast<float4*>(&Wis[row * DPAD + d4]) = v;
    }

    float biasv[4];
#pragma unroll
    for (int g = 0; g < 4; g++)
        biasv[g] = bih[g * HH + jg] + bhh[g * HH + jg];

    const int bl0 = bgrp + 8 * kh;
    const int bl1 = bgrp + 4 + 8 * kh;
    const int b0g = q * BC + bl0;
    const int b1g = q * BC + bl1;

    // x staging: publish x(0) into slot 0, prefetch x(1) into xreg
    const int xbl = tid >> 4, xd4 = (tid & 15) << 2;
    const float* xbase = &x[(size_t)(q * BC + xbl) * TT * DD + xd4];
    *reinterpret_cast<float4*>(&xs[xbl * DPAD + xd4]) =
        *reinterpret_cast<const float4*>(xbase);
    float4 xreg = *reinterpret_cast<const float4*>(xbase + DD);

    float c0 = 0.0f, c1 = 0.0f;
    __syncthreads();   // weights + xs slot0 ready (CTA-local)
    asm volatile("barrier.cluster.arrive.aligned;" ::: "memory");  // release h0

    for (int t = 0; t < TT; t++) {
        const float* xp0 = xs + (t & 1) * BC * DPAD;

        unsigned long long acc2[4][4];
#pragma unroll
        for (int g = 0; g < 4; g++)
#pragma unroll
            for (int i = 0; i < 4; i++) acc2[g][i] = 0ull;

        const float* wp = Wis + jl * DPAD + kh * 4;
        const float* xp = xp0 + bgrp * DPAD + kh * 4;

        // ---- input projection part A (hides cluster barrier skew) ----
#pragma unroll
        for (int cc = 0; cc < 4; cc++) {
            int d = cc * 8;
            ulonglong2 w0 = *reinterpret_cast<const ulonglong2*>(&wp[d + 0 * GJ * DPAD]);
            ulonglong2 w1 = *reinterpret_cast<const ulonglong2*>(&wp[d + 1 * GJ * DPAD]);
            ulonglong2 w2 = *reinterpret_cast<const ulonglong2*>(&wp[d + 2 * GJ * DPAD]);
            ulonglong2 w3 = *reinterpret_cast<const ulonglong2*>(&wp[d + 3 * GJ * DPAD]);
            ulonglong2 v0 = *reinterpret_cast<const ulonglong2*>(&xp[d + 0 * DPAD]);
            ulonglong2 v1 = *reinterpret_cast<const ulonglong2*>(&xp[d + 4 * DPAD]);
            ulonglong2 v2 = *reinterpret_cast<const ulonglong2*>(&xp[d + 8 * DPAD]);
            ulonglong2 v3 = *reinterpret_cast<const ulonglong2*>(&xp[d + 12 * DPAD]);
            ACCP(0,0,w0,v0); ACCP(0,1,w0,v1); ACCP(0,2,w0,v2); ACCP(0,3,w0,v3);
            ACCP(1,0,w1,v0); ACCP(1,1,w1,v1); ACCP(1,2,w1,v2); ACCP(1,3,w1,v3);
            ACCP(2,0,w2,v0); ACCP(2,1,w2,v1); ACCP(2,2,w2,v2); ACCP(2,3,w2,v3);
            ACCP(3,0,w3,v0); ACCP(3,1,w3,v1); ACCP(3,2,w3,v2); ACCP(3,3,w3,v3);
        }

        // ---- h(t-1) published by all peer CTAs ----
        asm volatile("barrier.cluster.wait.aligned;" ::: "memory");

        const float* hsrc = g_h[t & 1];
        float* hdst = g_h[(t + 1) & 1];

        // issue the h-tile loads NOW; latency hidden by input-proj part B
        float4 hreg[4];
#pragma unroll
        for (int ii = 0; ii < 4; ii++) {
            int f = tid + RTH * ii;            // [0,1024)
            int bl = f >> 6, c4 = (f & 63) << 2;
            hreg[ii] = __ldcg(reinterpret_cast<const float4*>(
                &hsrc[(q * BC + bl) * HH + c4]));
        }

        // ---- input projection part B ----
#pragma unroll
        for (int cc = 4; cc < 8; cc++) {
            int d = cc * 8;
            ulonglong2 w0 = *reinterpret_cast<const ulonglong2*>(&wp[d + 0 * GJ * DPAD]);
            ulonglong2 w1 = *reinterpret_cast<const ulonglong2*>(&wp[d + 1 * GJ * DPAD]);
            ulonglong2 w2 = *reinterpret_cast<const ulonglong2*>(&wp[d + 2 * GJ * DPAD]);
            ulonglong2 w3 = *reinterpret_cast<const ulonglong2*>(&wp[d + 3 * GJ * DPAD]);
            ulonglong2 v0 = *reinterpret_cast<const ulonglong2*>(&xp[d + 0 * DPAD]);
            ulonglong2 v1 = *reinterpret_cast<const ulonglong2*>(&xp[d + 4 * DPAD]);
            ulonglong2 v2 = *reinterpret_cast<const ulonglong2*>(&xp[d + 8 * DPAD]);
            ulonglong2 v3 = *reinterpret_cast<const ulonglong2*>(&xp[d + 12 * DPAD]);
            ACCP(0,0,w0,v0); ACCP(0,1,w0,v1); ACCP(0,2,w0,v2); ACCP(0,3,w0,v3);
            ACCP(1,0,w1,v0); ACCP(1,1,w1,v1); ACCP(1,2,w1,v2); ACCP(1,3,w1,v3);
            ACCP(2,0,w2,v0); ACCP(2,1,w2,v1); ACCP(2,2,w2,v2); ACCP(2,3,w2,v3);
            ACCP(3,0,w3,v0); ACCP(3,1,w3,v1); ACCP(3,2,w3,v2); ACCP(3,3,w3,v3);
        }

        // publish x(t+1) into the other slot; prefetch x(t+2)
        if (t + 1 < TT) {
            *reinterpret_cast<float4*>(
                &xs[((t + 1) & 1) * BC * DPAD + xbl * DPAD + xd4]) = xreg;
            if (t + 2 < TT)
                xreg = *reinterpret_cast<const float4*>(xbase + (size_t)(t + 2) * DD);
        }

        // stage h tile into shared
#pragma unroll
        for (int ii = 0; ii < 4; ii++) {
            int f = tid + RTH * ii;
            int bl = f >> 6, c4 = (f & 63) << 2;
            *reinterpret_cast<float4*>(&hs[bl * HPAD + c4]) = hreg[ii];
        }
        __syncthreads();   // hs + xs(t+1) ready

        // ---- recurrent part: k over H=256, this thread's half ----
        {
            const float* wph = Ws + jl * HPAD + kh * 4;
            const float* hp  = hs + bgrp * HPAD + kh * 4;
#pragma unroll 4
            for (int cc = 0; cc < 32; cc++) {
                int k = cc * 8;
                ulonglong2 w0 = *reinterpret_cast<const ulonglong2*>(&wph[k + 0 * GJ * HPAD]);
                ulonglong2 w1 = *reinterpret_cast<const ulonglong2*>(&wph[k + 1 * GJ * HPAD]);
                ulonglong2 w2 = *reinterpret_cast<const ulonglong2*>(&wph[k + 2 * GJ * HPAD]);
                ulonglong2 w3 = *reinterpret_cast<const ulonglong2*>(&wph[k + 3 * GJ * HPAD]);
                ulonglong2 v0 = *reinterpret_cast<const ulonglong2*>(&hp[k + 0 * HPAD]);
                ulonglong2 v1 = *reinterpret_cast<const ulonglong2*>(&hp[k + 4 * HPAD]);
                ulonglong2 v2 = *reinterpret_cast<const ulonglong2*>(&hp[k + 8 * HPAD]);
                ulonglong2 v3 = *reinterpret_cast<const ulonglong2*>(&hp[k + 12 * HPAD]);
                ACCP(0,0,w0,v0); ACCP(0,1,w0,v1); ACCP(0,2,w0,v2); ACCP(0,3,w0,v3);
                ACCP(1,0,w1,v0); ACCP(1,1,w1,v1); ACCP(1,2,w1,v2); ACCP(1,3,w1,v3);
                ACCP(2,0,w2,v0); ACCP(2,1,w2,v1); ACCP(2,2,w2,v2); ACCP(2,3,w2,v3);
                ACCP(3,0,w3,v0); ACCP(3,1,w3,v1); ACCP(3,2,w3,v2); ACCP(3,3,w3,v3);
            }
        }

        // ---- unpack packed partials, pair-reduce across the k-split ----
        float acc[4][4];
#pragma unroll
        for (int g = 0; g < 4; g++)
#pragma unroll
            for (int i = 0; i < 4; i++) {
                float lo = __uint_as_float((unsigned)acc2[g][i]);
                float hi = __uint_as_float((unsigned)(acc2[g][i] >> 32));
                float a = lo + hi;
                acc[g][i] = a + __shfl_xor_sync(0xffffffffu, a, 1);
            }

        // ---- pointwise LSTM update for owned batch rows ----
        float z0[4], z1[4];
#pragma unroll
        for (int g = 0; g < 4; g++) {
            z0[g] = (kh ? acc[g][2] : acc[g][0]) + biasv[g];
            z1[g] = (kh ? acc[g][3] : acc[g][1]) + biasv[g];
        }
        {
            float ig = sigm(z0[0]), fg = sigm(z0[1]);
            float gg = tanh_fast(z0[2]), og = sigm(z0[3]);
            c0 = fg * c0 + ig * gg;
            __stcg(&hdst[b0g * HH + jg], og * tanh_fast(c0));
        }
        {
            float ig = sigm(z1[0]), fg = sigm(z1[1]);
            float gg = tanh_fast(z1[2]), og = sigm(z1[3]);
            c1 = fg * c1 + ig * gg;
            __stcg(&hdst[b1g * HH + jg], og * tanh_fast(c1));
        }

        // release this step's h to the cluster
        asm volatile("barrier.cluster.arrive.aligned;" ::: "memory");
    }
    asm volatile("barrier.cluster.wait.aligned;" ::: "memory");

    // ---- output head: this CTA handles local batch rows {2r, 2r+1} ----
    // h_T = g_h[0] (TT even). 2 rows x 10 classes = 20 tasks over 8 warps.
    {
        const int w = tid >> 5, lane = tid & 31;
        for (int task = w; task < 2 * NCLASS; task += 8) {
            int row = task / NCLASS, cls = task % NCLASS;
            int b = q * BC + 2 * r + row;
            float s = 0.0f;
#pragma unroll
            for (int k = lane; k < HH; k += 32)
                s += __ldcg(&g_h[0][b * HH + k]) * Wout[cls * HH + k];
#pragma unroll
            for (int o = 16; o; o >>= 1) s += __shfl_xor_sync(0xffffffffu, s, o);
            if (lane == 0) out[b * NCLASS + cls] = sigm(s + bout[cls]);
        }
    }
}

extern "C" void kernel_launch(void* const* d_in, const int* in_sizes, int n_in,
                              void* d_out, int out_size) {
    const float* x    = (const float*)d_in[0];
    const float* Wih  = (const float*)d_in[1];
    const float* Whh  = (const float*)d_in[2];
    const float* bih  = (const float*)d_in[3];
    const float* bhh  = (const float*)d_in[4];
    const float* Wout = (const float*)d_in[5];
    const float* bout = (const float*)d_in[6];
    float* out = (float*)d_out;

    cudaFuncSetAttribute(lstm_kernel,
                         cudaFuncAttributeMaxDynamicSharedMemorySize, REC_SMEM);

    lstm_kernel<<<NC * CS, RTH, REC_SMEM>>>(x, Wih, Whh, bih, bhh,
                                            Wout, bout, out);
}